// round 11
// baseline (speedup 1.0000x reference)
#include <cuda_runtime.h>

#define LN_EPS 1e-12f

// ===========================================================================
// Kernel A: embd2 fill (store-bound role). 2048 blocks, 2 rows each.
// ===========================================================================
__global__ void k_embd2(const int* __restrict__ tty,
                        const float* __restrict__ Wrel,
                        float* __restrict__ out2) {
    __shared__ float lnrel[130 * 64];
    __shared__ int   sid[2][512];
    __shared__ int   stype[512];

    const int t    = threadIdx.x;
    const int warp = t >> 5, lane = t & 31;
    const int R0   = blockIdx.x * 2;          // rows R0, R0+1 (same batch)
    const int b    = R0 >> 9;
    const int i0   = R0 & 511;

    // LN(W_rel) table: warp-per-row, 17 passes
    for (int p = 0; p < 17; p++) {
        int row = p * 8 + warp;
        if (row < 130) {
            float x0 = Wrel[row * 64 + lane];
            float x1 = Wrel[row * 64 + 32 + lane];
            float s = x0 + x1, q = x0 * x0 + x1 * x1;
            #pragma unroll
            for (int o = 16; o; o >>= 1) {
                s += __shfl_xor_sync(0xffffffffu, s, o);
                q += __shfl_xor_sync(0xffffffffu, q, o);
            }
            float mean = s * (1.0f / 64.0f);
            float inv  = rsqrtf(q * (1.0f / 64.0f) - mean * mean + LN_EPS);
            lnrel[row * 64 + lane]      = (x0 - mean) * inv;
            lnrel[row * 64 + 32 + lane] = (x1 - mean) * inv;
        }
    }
    for (int j = t; j < 512; j += 256) stype[j] = tty[b * 512 + j];
    __syncthreads();

    for (int rr = 0; rr < 2; rr++) {
        int i  = i0 + rr;
        int ti = stype[i];
        for (int j = t; j < 512; j += 256) {
            int id;
            if (j == i)               id = -1;           // diag: skip
            else if (i == 0)          id = 128;
            else if (j == 0)          id = 129;
            else if (stype[j] != ti)  id = 64;
            else {
                int d = i - j;
                id = (d > 0) ? 128 - min(d, 63) : min(-d, 63);
            }
            sid[rr][j] = (id < 0) ? -1 : (id << 4);      // float4 offset
        }
    }
    __syncthreads();

    // hot loop: explicit 4-wide batching for store-stream MLP
    const float4* ln4 = reinterpret_cast<const float4*>(lnrel);
    float4* outp = reinterpret_cast<float4*>(out2) + (size_t)R0 * (512 * 16);
    const int* sidp = &sid[0][0];
    const int d4  = t & 15;
    const int jr0 = t >> 4;
    #pragma unroll 4
    for (int g = 0; g < 16; g++) {
        int base = g * 64 + jr0;
        int s0 = sidp[base];
        int s1 = sidp[base + 16];
        int s2 = sidp[base + 32];
        int s3 = sidp[base + 48];
        float4 v0 = ln4[max(s0, 0) + d4];
        float4 v1 = ln4[max(s1, 0) + d4];
        float4 v2 = ln4[max(s2, 0) + d4];
        float4 v3 = ln4[max(s3, 0) + d4];
        float4* o = outp + base * 16 + d4;
        if (s0 >= 0) __stcs(o,           v0);
        if (s1 >= 0) __stcs(o + 16 * 16, v1);
        if (s2 >= 0) __stcs(o + 32 * 16, v2);
        if (s3 >= 0) __stcs(o + 48 * 16, v3);
    }
}

// ===========================================================================
// Kernel B: compute role. 512 blocks, 8 rows each (embd1 + diag + out0).
// ===========================================================================
__global__ void __launch_bounds__(256) k_comp(
    const int* __restrict__ tok, const int* __restrict__ tty,
    const float* __restrict__ Wword, const float* __restrict__ Wtype,
    const float* __restrict__ Wabs,  const float* __restrict__ Wrel,
    const float* __restrict__ Wglob, const float* __restrict__ Wdiag,
    const float* __restrict__ bdiag,
    float* __restrict__ out0, float* __restrict__ out1,
    float* __restrict__ out2) {

    __shared__ float sx[8][768];
    __shared__ union {
        float sWd[64][65];
        float sred[8][8][64];
    } u;
    __shared__ float sy[8][64];
    __shared__ float wsum[8], wsq[8];
    __shared__ float stat[2];

    const int t    = threadIdx.x;
    const int warp = t >> 5, lane = t & 31;
    const int cid  = blockIdx.x;
    const int row0 = cid * 8;

    // out0 duty: blocks 0..7 LN 8 rows of W_glob each, broadcast x8 batches
    if (cid < 8) {
        int g = cid * 8 + warp;
        float x0 = Wglob[g * 64 + lane];
        float x1 = Wglob[g * 64 + 32 + lane];
        float s = x0 + x1, q = x0 * x0 + x1 * x1;
        #pragma unroll
        for (int o = 16; o; o >>= 1) {
            s += __shfl_xor_sync(0xffffffffu, s, o);
            q += __shfl_xor_sync(0xffffffffu, q, o);
        }
        float mean = s * (1.0f / 64.0f);
        float inv  = rsqrtf(q * (1.0f / 64.0f) - mean * mean + LN_EPS);
        float v0 = (x0 - mean) * inv, v1 = (x1 - mean) * inv;
        #pragma unroll
        for (int bb = 0; bb < 8; bb++) {
            out0[(bb * 64 + g) * 64 + lane]      = v0;
            out0[(bb * 64 + g) * 64 + 32 + lane] = v1;
        }
    }

    // ---- phase 1: gather + LN embd1 (8 rows) ----
    for (int r = 0; r < 8; r++) {
        int row = row0 + r;
        int s   = row & 511;
        int tk  = tok[row], ty = tty[row];
        const float* pw = Wword + (size_t)tk * 768;
        const float* pt = Wtype + (size_t)ty * 768;
        const float* pa = Wabs  + (size_t)s  * 768;
        float v0 = pw[t      ] + pt[t      ] + pa[t      ];
        float v1 = pw[t + 256] + pt[t + 256] + pa[t + 256];
        float v2 = pw[t + 512] + pt[t + 512] + pa[t + 512];
        sx[r][t] = v0; sx[r][t + 256] = v1; sx[r][t + 512] = v2;

        float s1 = v0 + v1 + v2;
        float q1 = v0 * v0 + v1 * v1 + v2 * v2;
        #pragma unroll
        for (int o = 16; o; o >>= 1) {
            s1 += __shfl_down_sync(0xffffffffu, s1, o);
            q1 += __shfl_down_sync(0xffffffffu, q1, o);
        }
        if (lane == 0) { wsum[warp] = s1; wsq[warp] = q1; }
        __syncthreads();
        if (t == 0) {
            float S = 0.f, Q = 0.f;
            #pragma unroll
            for (int w = 0; w < 8; w++) { S += wsum[w]; Q += wsq[w]; }
            float mean = S * (1.0f / 768.0f);
            float var  = Q * (1.0f / 768.0f) - mean * mean;
            stat[0] = mean; stat[1] = rsqrtf(var + LN_EPS);
        }
        __syncthreads();
        float mean = stat[0], inv = stat[1];
        float* o = out1 + (size_t)row * 768;
        o[t      ] = (v0 - mean) * inv;
        o[t + 256] = (v1 - mean) * inv;
        o[t + 512] = (v2 - mean) * inv;
        __syncthreads();
    }

    // ---- phase 2: diag GEMV, 8-row register blocking ----
    float acc0[8], acc1[8];
    #pragma unroll
    for (int r = 0; r < 8; r++) { acc0[r] = 0.f; acc1[r] = 0.f; }

    for (int c = 0; c < 12; c++) {
        __syncthreads();
        for (int e = t; e < 64 * 64; e += 256) {
            int k = e & 63, d = e >> 6;
            u.sWd[k][d] = Wdiag[(size_t)d * 768 + c * 64 + k];
        }
        __syncthreads();
        int kbase = warp * 8;
        #pragma unroll
        for (int kk = 0; kk < 8; kk++) {
            float w0 = u.sWd[kbase + kk][lane];
            float w1 = u.sWd[kbase + kk][lane + 32];
            int kg = c * 64 + kbase + kk;
            #pragma unroll
            for (int r = 0; r < 8; r++) {
                float xv = sx[r][kg];
                acc0[r] += xv * w0;
                acc1[r] += xv * w1;
            }
        }
    }

    __syncthreads();
    #pragma unroll
    for (int r = 0; r < 8; r++) {
        u.sred[warp][r][lane]      = acc0[r];
        u.sred[warp][r][lane + 32] = acc1[r];
    }
    __syncthreads();
    for (int o = t; o < 512; o += 256) {
        int r = o >> 6, d = o & 63;
        float s = 0.f;
        #pragma unroll
        for (int w = 0; w < 8; w++) s += u.sred[w][r][d];
        sy[r][d] = s + Wrel[d] + bdiag[d];
    }
    __syncthreads();

    {
        float y0 = sy[warp][lane];
        float y1 = sy[warp][lane + 32];
        float S = y0 + y1, Q = y0 * y0 + y1 * y1;
        #pragma unroll
        for (int o = 16; o; o >>= 1) {
            S += __shfl_xor_sync(0xffffffffu, S, o);
            Q += __shfl_xor_sync(0xffffffffu, Q, o);
        }
        float mean = S * (1.0f / 64.0f);
        float inv  = rsqrtf(Q * (1.0f / 64.0f) - mean * mean + LN_EPS);
        int row = row0 + warp;
        int s   = row & 511;
        float* od = out2 + ((size_t)row * 512 + s) * 64;
        od[lane]      = (y0 - mean) * inv;
        od[lane + 32] = (y1 - mean) * inv;
    }
}

// ---------------------------------------------------------------------------
extern "C" void kernel_launch(void* const* d_in, const int* in_sizes, int n_in,
                              void* d_out, int out_size) {
    const int*   tok   = (const int*)d_in[0];
    const int*   tty   = (const int*)d_in[1];
    const float* Wword = (const float*)d_in[2];
    const float* Wtype = (const float*)d_in[3];
    const float* Wabs  = (const float*)d_in[4];
    const float* Wrel  = (const float*)d_in[5];
    const float* Wglob = (const float*)d_in[6];
    const float* Wdiag = (const float*)d_in[7];
    const float* bdiag = (const float*)d_in[8];

    float* out  = (float*)d_out;
    float* out0 = out;                      // [8,64,64]
    float* out1 = out0 + 8 * 64 * 64;       // [8,512,768]
    float* out2 = out1 + 8 * 512 * 768;     // [8,512,512,64]

    // fork-join: store kernel launches FIRST (owns the machine from t=0);
    // compute kernel runs on a LOW-PRIORITY stream, filling retiring slots.
    static cudaStream_t s2 = nullptr;
    static cudaEvent_t  efork = nullptr, ejoin = nullptr;
    if (!s2) {
        int loPrio = 0, hiPrio = 0;
        cudaDeviceGetStreamPriorityRange(&loPrio, &hiPrio);
        cudaStreamCreateWithPriority(&s2, cudaStreamNonBlocking, loPrio);
        cudaEventCreateWithFlags(&efork, cudaEventDisableTiming);
        cudaEventCreateWithFlags(&ejoin, cudaEventDisableTiming);
    }

    cudaEventRecord(efork, 0);
    cudaStreamWaitEvent(s2, efork, 0);

    k_embd2<<<2048, 256>>>(tty, Wrel, out2);

    k_comp<<<512, 256, 0, s2>>>(tok, tty, Wword, Wtype, Wabs, Wrel, Wglob,
                                Wdiag, bdiag, out0, out1, out2);
    cudaEventRecord(ejoin, s2);

    cudaStreamWaitEvent(0, ejoin, 0);
}

// round 13
// speedup vs baseline: 1.0682x; 1.0682x over previous
#include <cuda_runtime.h>

#define LN_EPS 1e-12f

// ===========================================================================
// Kernel A: embd2 fill (store-bound role). 2048 blocks, 2 rows each.
// ===========================================================================
__global__ void k_embd2(const int* __restrict__ tty,
                        const float* __restrict__ Wrel,
                        float* __restrict__ out2) {
    __shared__ float lnrel[130 * 64];
    __shared__ int   sid[2][512];
    __shared__ int   stype[512];

    const int t    = threadIdx.x;
    const int warp = t >> 5, lane = t & 31;
    const int R0   = blockIdx.x * 2;          // rows R0, R0+1 (same batch)
    const int b    = R0 >> 9;
    const int i0   = R0 & 511;

    // LN(W_rel) table: warp-per-row, 17 passes
    for (int p = 0; p < 17; p++) {
        int row = p * 8 + warp;
        if (row < 130) {
            float x0 = Wrel[row * 64 + lane];
            float x1 = Wrel[row * 64 + 32 + lane];
            float s = x0 + x1, q = x0 * x0 + x1 * x1;
            #pragma unroll
            for (int o = 16; o; o >>= 1) {
                s += __shfl_xor_sync(0xffffffffu, s, o);
                q += __shfl_xor_sync(0xffffffffu, q, o);
            }
            float mean = s * (1.0f / 64.0f);
            float inv  = rsqrtf(q * (1.0f / 64.0f) - mean * mean + LN_EPS);
            lnrel[row * 64 + lane]      = (x0 - mean) * inv;
            lnrel[row * 64 + 32 + lane] = (x1 - mean) * inv;
        }
    }
    for (int j = t; j < 512; j += 256) stype[j] = tty[b * 512 + j];
    __syncthreads();

    for (int rr = 0; rr < 2; rr++) {
        int i  = i0 + rr;
        int ti = stype[i];
        for (int j = t; j < 512; j += 256) {
            int id;
            if (j == i)               id = -1;           // diag: skip
            else if (i == 0)          id = 128;
            else if (j == 0)          id = 129;
            else if (stype[j] != ti)  id = 64;
            else {
                int d = i - j;
                id = (d > 0) ? 128 - min(d, 63) : min(-d, 63);
            }
            sid[rr][j] = (id < 0) ? -1 : (id << 4);      // float4 offset
        }
    }
    __syncthreads();

    // hot loop: explicit 4-wide batching for store-stream MLP
    const float4* ln4 = reinterpret_cast<const float4*>(lnrel);
    float4* outp = reinterpret_cast<float4*>(out2) + (size_t)R0 * (512 * 16);
    const int* sidp = &sid[0][0];
    const int d4  = t & 15;
    const int jr0 = t >> 4;
    #pragma unroll 4
    for (int g = 0; g < 16; g++) {
        int base = g * 64 + jr0;
        int s0 = sidp[base];
        int s1 = sidp[base + 16];
        int s2 = sidp[base + 32];
        int s3 = sidp[base + 48];
        float4 v0 = ln4[max(s0, 0) + d4];
        float4 v1 = ln4[max(s1, 0) + d4];
        float4 v2 = ln4[max(s2, 0) + d4];
        float4 v3 = ln4[max(s3, 0) + d4];
        float4* o = outp + base * 16 + d4;
        if (s0 >= 0) __stcs(o,           v0);
        if (s1 >= 0) __stcs(o + 16 * 16, v1);
        if (s2 >= 0) __stcs(o + 32 * 16, v2);
        if (s3 >= 0) __stcs(o + 48 * 16, v3);
    }
}

// ===========================================================================
// Kernel B: compute role. 512 blocks, 8 rows each. Phase 1 is warp-per-row
// (barrier-free); phase 2 is the 8-row register-blocked GEMV.
// ===========================================================================
__global__ void __launch_bounds__(256) k_comp(
    const int* __restrict__ tok, const int* __restrict__ tty,
    const float* __restrict__ Wword, const float* __restrict__ Wtype,
    const float* __restrict__ Wabs,  const float* __restrict__ Wrel,
    const float* __restrict__ Wglob, const float* __restrict__ Wdiag,
    const float* __restrict__ bdiag,
    float* __restrict__ out0, float* __restrict__ out1,
    float* __restrict__ out2) {

    __shared__ float sx[8][768];
    __shared__ union {
        float sWd[64][65];
        float sred[8][8][64];
    } u;
    __shared__ float sy[8][64];

    const int t    = threadIdx.x;
    const int warp = t >> 5, lane = t & 31;
    const int cid  = blockIdx.x;
    const int row0 = cid * 8;

    // out0 duty: blocks 0..7 LN 8 rows of W_glob each, broadcast x8 batches
    if (cid < 8) {
        int g = cid * 8 + warp;
        float x0 = Wglob[g * 64 + lane];
        float x1 = Wglob[g * 64 + 32 + lane];
        float s = x0 + x1, q = x0 * x0 + x1 * x1;
        #pragma unroll
        for (int o = 16; o; o >>= 1) {
            s += __shfl_xor_sync(0xffffffffu, s, o);
            q += __shfl_xor_sync(0xffffffffu, q, o);
        }
        float mean = s * (1.0f / 64.0f);
        float inv  = rsqrtf(q * (1.0f / 64.0f) - mean * mean + LN_EPS);
        float v0 = (x0 - mean) * inv, v1 = (x1 - mean) * inv;
        #pragma unroll
        for (int bb = 0; bb < 8; bb++) {
            out0[(bb * 64 + g) * 64 + lane]      = v0;
            out0[(bb * 64 + g) * 64 + 32 + lane] = v1;
        }
    }

    // ---- phase 1: warp-per-row gather + LN (no block barriers) ----
    {
        int row = row0 + warp;
        int s   = row & 511;
        int tk  = tok[row], ty = tty[row];
        const float* pw = Wword + (size_t)tk * 768;
        const float* pt = Wtype + (size_t)ty * 768;
        const float* pa = Wabs  + (size_t)s  * 768;

        float v[24];
        float s1 = 0.f, q1 = 0.f;
        #pragma unroll
        for (int m = 0; m < 24; m++) {
            int idx = lane + 32 * m;
            float x = pw[idx] + pt[idx] + pa[idx];
            v[m] = x;
            s1 += x;
            q1 += x * x;
        }
        #pragma unroll
        for (int o = 16; o; o >>= 1) {
            s1 += __shfl_xor_sync(0xffffffffu, s1, o);
            q1 += __shfl_xor_sync(0xffffffffu, q1, o);
        }
        float mean = s1 * (1.0f / 768.0f);
        float var  = q1 * (1.0f / 768.0f) - mean * mean;
        float inv  = rsqrtf(var + LN_EPS);

        float* o = out1 + (size_t)row * 768;
        #pragma unroll
        for (int m = 0; m < 24; m++) {
            int idx = lane + 32 * m;
            sx[warp][idx] = v[m];
            o[idx] = (v[m] - mean) * inv;
        }
    }

    // ---- phase 2: diag GEMV, 8-row register blocking ----
    float acc0[8], acc1[8];
    #pragma unroll
    for (int r = 0; r < 8; r++) { acc0[r] = 0.f; acc1[r] = 0.f; }

    for (int c = 0; c < 12; c++) {
        __syncthreads();
        for (int e = t; e < 64 * 64; e += 256) {
            int k = e & 63, d = e >> 6;
            u.sWd[k][d] = Wdiag[(size_t)d * 768 + c * 64 + k];
        }
        __syncthreads();
        int kbase = warp * 8;
        #pragma unroll
        for (int kk = 0; kk < 8; kk++) {
            float w0 = u.sWd[kbase + kk][lane];
            float w1 = u.sWd[kbase + kk][lane + 32];
            int kg = c * 64 + kbase + kk;
            #pragma unroll
            for (int r = 0; r < 8; r++) {
                float xv = sx[r][kg];
                acc0[r] += xv * w0;
                acc1[r] += xv * w1;
            }
        }
    }

    __syncthreads();
    #pragma unroll
    for (int r = 0; r < 8; r++) {
        u.sred[warp][r][lane]      = acc0[r];
        u.sred[warp][r][lane + 32] = acc1[r];
    }
    __syncthreads();
    for (int o = t; o < 512; o += 256) {
        int r = o >> 6, d = o & 63;
        float s = 0.f;
        #pragma unroll
        for (int w = 0; w < 8; w++) s += u.sred[w][r][d];
        sy[r][d] = s + Wrel[d] + bdiag[d];
    }
    __syncthreads();

    {
        float y0 = sy[warp][lane];
        float y1 = sy[warp][lane + 32];
        float S = y0 + y1, Q = y0 * y0 + y1 * y1;
        #pragma unroll
        for (int o = 16; o; o >>= 1) {
            S += __shfl_xor_sync(0xffffffffu, S, o);
            Q += __shfl_xor_sync(0xffffffffu, Q, o);
        }
        float mean = S * (1.0f / 64.0f);
        float inv  = rsqrtf(Q * (1.0f / 64.0f) - mean * mean + LN_EPS);
        int row = row0 + warp;
        int s   = row & 511;
        float* od = out2 + ((size_t)row * 512 + s) * 64;
        od[lane]      = (y0 - mean) * inv;
        od[lane + 32] = (y1 - mean) * inv;
    }
}

// ---------------------------------------------------------------------------
extern "C" void kernel_launch(void* const* d_in, const int* in_sizes, int n_in,
                              void* d_out, int out_size) {
    const int*   tok   = (const int*)d_in[0];
    const int*   tty   = (const int*)d_in[1];
    const float* Wword = (const float*)d_in[2];
    const float* Wtype = (const float*)d_in[3];
    const float* Wabs  = (const float*)d_in[4];
    const float* Wrel  = (const float*)d_in[5];
    const float* Wglob = (const float*)d_in[6];
    const float* Wdiag = (const float*)d_in[7];
    const float* bdiag = (const float*)d_in[8];

    float* out  = (float*)d_out;
    float* out0 = out;                      // [8,64,64]
    float* out1 = out0 + 8 * 64 * 64;       // [8,512,768]
    float* out2 = out1 + 8 * 512 * 768;     // [8,512,512,64]

    // comp launches first on LOW priority; embd2 on HIGH priority so the
    // distributor prefers its blocks for every freed slot.
    static cudaStream_t sLo = nullptr, sHi = nullptr;
    static cudaEvent_t  efork = nullptr, e1 = nullptr, e2 = nullptr;
    if (!sLo) {
        int loPrio = 0, hiPrio = 0;
        cudaDeviceGetStreamPriorityRange(&loPrio, &hiPrio);
        cudaStreamCreateWithPriority(&sLo, cudaStreamNonBlocking, loPrio);
        cudaStreamCreateWithPriority(&sHi, cudaStreamNonBlocking, hiPrio);
        cudaEventCreateWithFlags(&efork, cudaEventDisableTiming);
        cudaEventCreateWithFlags(&e1, cudaEventDisableTiming);
        cudaEventCreateWithFlags(&e2, cudaEventDisableTiming);
    }

    cudaEventRecord(efork, 0);
    cudaStreamWaitEvent(sLo, efork, 0);
    cudaStreamWaitEvent(sHi, efork, 0);

    k_comp<<<512, 256, 0, sLo>>>(tok, tty, Wword, Wtype, Wabs, Wrel, Wglob,
                                 Wdiag, bdiag, out0, out1, out2);
    cudaEventRecord(e1, sLo);

    k_embd2<<<2048, 256, 0, sHi>>>(tty, Wrel, out2);
    cudaEventRecord(e2, sHi);

    cudaStreamWaitEvent(0, e1, 0);
    cudaStreamWaitEvent(0, e2, 0);
}

// round 15
// speedup vs baseline: 1.1758x; 1.1007x over previous
#include <cuda_runtime.h>

#define LN_EPS 1e-12f

// ===========================================================================
// Kernel A: embd2 fill. 1024 blocks x 512 threads, 4 rows each.
// ===========================================================================
__global__ void k_embd2(const int* __restrict__ tty,
                        const float* __restrict__ Wrel,
                        float* __restrict__ out2) {
    __shared__ float lnrel[130 * 64];
    __shared__ int   sid[4][512];
    __shared__ int   stype[512];

    const int t    = threadIdx.x;             // 0..511
    const int warp = t >> 5, lane = t & 31;   // 16 warps
    const int R0   = blockIdx.x * 4;          // rows R0..R0+3 (same batch)
    const int b    = R0 >> 9;
    const int i0   = R0 & 511;

    // LN(W_rel) table: warp-per-row, 9 passes over 16 warps
    for (int p = 0; p < 9; p++) {
        int row = p * 16 + warp;
        if (row < 130) {
            float x0 = Wrel[row * 64 + lane];
            float x1 = Wrel[row * 64 + 32 + lane];
            float s = x0 + x1, q = x0 * x0 + x1 * x1;
            #pragma unroll
            for (int o = 16; o; o >>= 1) {
                s += __shfl_xor_sync(0xffffffffu, s, o);
                q += __shfl_xor_sync(0xffffffffu, q, o);
            }
            float mean = s * (1.0f / 64.0f);
            float inv  = rsqrtf(q * (1.0f / 64.0f) - mean * mean + LN_EPS);
            lnrel[row * 64 + lane]      = (x0 - mean) * inv;
            lnrel[row * 64 + 32 + lane] = (x1 - mean) * inv;
        }
    }
    stype[t] = tty[b * 512 + t];
    __syncthreads();

    {
        int j  = t;
        int tj = stype[j];
        #pragma unroll
        for (int rr = 0; rr < 4; rr++) {
            int i  = i0 + rr;
            int ti = stype[i];
            int id;
            if (j == i)               id = -1;           // diag: skip
            else if (i == 0)          id = 128;
            else if (j == 0)          id = 129;
            else if (tj != ti)        id = 64;
            else {
                int d = i - j;
                id = (d > 0) ? 128 - min(d, 63) : min(-d, 63);
            }
            sid[rr][j] = (id < 0) ? -1 : (id << 4);      // float4 offset
        }
    }
    __syncthreads();

    // hot loop: explicit 4-wide batching for store-stream MLP
    const float4* ln4 = reinterpret_cast<const float4*>(lnrel);
    float4* outp = reinterpret_cast<float4*>(out2) + (size_t)R0 * (512 * 16);
    const int* sidp = &sid[0][0];
    const int d4  = t & 15;
    const int jr0 = t >> 4;                   // 0..31
    #pragma unroll 4
    for (int g = 0; g < 16; g++) {
        int base = g * 128 + jr0;             // jr for u=0; +32 per u
        int s0 = sidp[base];
        int s1 = sidp[base + 32];
        int s2 = sidp[base + 64];
        int s3 = sidp[base + 96];
        float4 v0 = ln4[max(s0, 0) + d4];
        float4 v1 = ln4[max(s1, 0) + d4];
        float4 v2 = ln4[max(s2, 0) + d4];
        float4 v3 = ln4[max(s3, 0) + d4];
        float4* o = outp + base * 16 + d4;
        if (s0 >= 0) __stcs(o,           v0);
        if (s1 >= 0) __stcs(o + 32 * 16, v1);
        if (s2 >= 0) __stcs(o + 64 * 16, v2);
        if (s3 >= 0) __stcs(o + 96 * 16, v3);
    }
}

// ===========================================================================
// Kernel B: compute role. 512 blocks, 8 rows each. Phase 1 warp-per-row.
// ===========================================================================
__global__ void __launch_bounds__(256) k_comp(
    const int* __restrict__ tok, const int* __restrict__ tty,
    const float* __restrict__ Wword, const float* __restrict__ Wtype,
    const float* __restrict__ Wabs,  const float* __restrict__ Wrel,
    const float* __restrict__ Wglob, const float* __restrict__ Wdiag,
    const float* __restrict__ bdiag,
    float* __restrict__ out0, float* __restrict__ out1,
    float* __restrict__ out2) {

    __shared__ float sx[8][768];
    __shared__ union {
        float sWd[64][65];
        float sred[8][8][64];
    } u;
    __shared__ float sy[8][64];

    const int t    = threadIdx.x;
    const int warp = t >> 5, lane = t & 31;
    const int cid  = blockIdx.x;
    const int row0 = cid * 8;

    if (cid < 8) {
        int g = cid * 8 + warp;
        float x0 = Wglob[g * 64 + lane];
        float x1 = Wglob[g * 64 + 32 + lane];
        float s = x0 + x1, q = x0 * x0 + x1 * x1;
        #pragma unroll
        for (int o = 16; o; o >>= 1) {
            s += __shfl_xor_sync(0xffffffffu, s, o);
            q += __shfl_xor_sync(0xffffffffu, q, o);
        }
        float mean = s * (1.0f / 64.0f);
        float inv  = rsqrtf(q * (1.0f / 64.0f) - mean * mean + LN_EPS);
        float v0 = (x0 - mean) * inv, v1 = (x1 - mean) * inv;
        #pragma unroll
        for (int bb = 0; bb < 8; bb++) {
            out0[(bb * 64 + g) * 64 + lane]      = v0;
            out0[(bb * 64 + g) * 64 + 32 + lane] = v1;
        }
    }

    // ---- phase 1: warp-per-row gather + LN (no block barriers) ----
    {
        int row = row0 + warp;
        int s   = row & 511;
        int tk  = tok[row], ty = tty[row];
        const float* pw = Wword + (size_t)tk * 768;
        const float* pt = Wtype + (size_t)ty * 768;
        const float* pa = Wabs  + (size_t)s  * 768;

        float v[24];
        float s1 = 0.f, q1 = 0.f;
        #pragma unroll
        for (int m = 0; m < 24; m++) {
            int idx = lane + 32 * m;
            float x = pw[idx] + pt[idx] + pa[idx];
            v[m] = x;
            s1 += x;
            q1 += x * x;
        }
        #pragma unroll
        for (int o = 16; o; o >>= 1) {
            s1 += __shfl_xor_sync(0xffffffffu, s1, o);
            q1 += __shfl_xor_sync(0xffffffffu, q1, o);
        }
        float mean = s1 * (1.0f / 768.0f);
        float var  = q1 * (1.0f / 768.0f) - mean * mean;
        float inv  = rsqrtf(var + LN_EPS);

        float* o = out1 + (size_t)row * 768;
        #pragma unroll
        for (int m = 0; m < 24; m++) {
            int idx = lane + 32 * m;
            sx[warp][idx] = v[m];
            o[idx] = (v[m] - mean) * inv;
        }
    }

    // ---- phase 2: diag GEMV, 8-row register blocking ----
    float acc0[8], acc1[8];
    #pragma unroll
    for (int r = 0; r < 8; r++) { acc0[r] = 0.f; acc1[r] = 0.f; }

    for (int c = 0; c < 12; c++) {
        __syncthreads();
        for (int e = t; e < 64 * 64; e += 256) {
            int k = e & 63, d = e >> 6;
            u.sWd[k][d] = Wdiag[(size_t)d * 768 + c * 64 + k];
        }
        __syncthreads();
        int kbase = warp * 8;
        #pragma unroll
        for (int kk = 0; kk < 8; kk++) {
            float w0 = u.sWd[kbase + kk][lane];
            float w1 = u.sWd[kbase + kk][lane + 32];
            int kg = c * 64 + kbase + kk;
            #pragma unroll
            for (int r = 0; r < 8; r++) {
                float xv = sx[r][kg];
                acc0[r] += xv * w0;
                acc1[r] += xv * w1;
            }
        }
    }

    __syncthreads();
    #pragma unroll
    for (int r = 0; r < 8; r++) {
        u.sred[warp][r][lane]      = acc0[r];
        u.sred[warp][r][lane + 32] = acc1[r];
    }
    __syncthreads();
    for (int o = t; o < 512; o += 256) {
        int r = o >> 6, d = o & 63;
        float s = 0.f;
        #pragma unroll
        for (int w = 0; w < 8; w++) s += u.sred[w][r][d];
        sy[r][d] = s + Wrel[d] + bdiag[d];
    }
    __syncthreads();

    {
        float y0 = sy[warp][lane];
        float y1 = sy[warp][lane + 32];
        float S = y0 + y1, Q = y0 * y0 + y1 * y1;
        #pragma unroll
        for (int o = 16; o; o >>= 1) {
            S += __shfl_xor_sync(0xffffffffu, S, o);
            Q += __shfl_xor_sync(0xffffffffu, Q, o);
        }
        float mean = S * (1.0f / 64.0f);
        float inv  = rsqrtf(Q * (1.0f / 64.0f) - mean * mean + LN_EPS);
        int row = row0 + warp;
        int s   = row & 511;
        float* od = out2 + ((size_t)row * 512 + s) * 64;
        od[lane]      = (y0 - mean) * inv;
        od[lane + 32] = (y1 - mean) * inv;
    }
}

// ---------------------------------------------------------------------------
extern "C" void kernel_launch(void* const* d_in, const int* in_sizes, int n_in,
                              void* d_out, int out_size) {
    const int*   tok   = (const int*)d_in[0];
    const int*   tty   = (const int*)d_in[1];
    const float* Wword = (const float*)d_in[2];
    const float* Wtype = (const float*)d_in[3];
    const float* Wabs  = (const float*)d_in[4];
    const float* Wrel  = (const float*)d_in[5];
    const float* Wglob = (const float*)d_in[6];
    const float* Wdiag = (const float*)d_in[7];
    const float* bdiag = (const float*)d_in[8];

    float* out  = (float*)d_out;
    float* out0 = out;                      // [8,64,64]
    float* out1 = out0 + 8 * 64 * 64;       // [8,512,768]
    float* out2 = out1 + 8 * 512 * 768;     // [8,512,512,64]

    static cudaStream_t sLo = nullptr, sHi = nullptr;
    static cudaEvent_t  efork = nullptr, e1 = nullptr, e2 = nullptr;
    if (!sLo) {
        int loPrio = 0, hiPrio = 0;
        cudaDeviceGetStreamPriorityRange(&loPrio, &hiPrio);
        cudaStreamCreateWithPriority(&sLo, cudaStreamNonBlocking, loPrio);
        cudaStreamCreateWithPriority(&sHi, cudaStreamNonBlocking, hiPrio);
        cudaEventCreateWithFlags(&efork, cudaEventDisableTiming);
        cudaEventCreateWithFlags(&e1, cudaEventDisableTiming);
        cudaEventCreateWithFlags(&e2, cudaEventDisableTiming);
    }

    cudaEventRecord(efork, 0);
    cudaStreamWaitEvent(sLo, efork, 0);
    cudaStreamWaitEvent(sHi, efork, 0);

    k_comp<<<512, 256, 0, sLo>>>(tok, tty, Wword, Wtype, Wabs, Wrel, Wglob,
                                 Wdiag, bdiag, out0, out1, out2);
    cudaEventRecord(e1, sLo);

    k_embd2<<<1024, 512, 0, sHi>>>(tty, Wrel, out2);
    cudaEventRecord(e2, sHi);

    cudaStreamWaitEvent(0, e1, 0);
    cudaStreamWaitEvent(0, e2, 0);
}

// round 16
// speedup vs baseline: 1.2233x; 1.0405x over previous
#include <cuda_runtime.h>

#define LN_EPS 1e-12f
#define N_PANELS 4096

__device__ int g_ctr;   // panel work-stealing counter (memset to 0 each launch)

// ===========================================================================
// Kernel A: persistent embd2 fill. grid = 4*num_SMs x 512 threads.
// Each block builds the LN(W_rel) table once, then steals 1-row panels.
// ===========================================================================
__global__ void k_embd2(const int* __restrict__ tty,
                        const float* __restrict__ Wrel,
                        float* __restrict__ out2) {
    __shared__ float lnrel[130 * 64];
    __shared__ int   sid[512];
    __shared__ int   sp;

    const int t    = threadIdx.x;             // 0..511
    const int warp = t >> 5, lane = t & 31;   // 16 warps

    // LN(W_rel) table: warp-per-row, 9 passes over 16 warps
    for (int p = 0; p < 9; p++) {
        int row = p * 16 + warp;
        if (row < 130) {
            float x0 = Wrel[row * 64 + lane];
            float x1 = Wrel[row * 64 + 32 + lane];
            float s = x0 + x1, q = x0 * x0 + x1 * x1;
            #pragma unroll
            for (int o = 16; o; o >>= 1) {
                s += __shfl_xor_sync(0xffffffffu, s, o);
                q += __shfl_xor_sync(0xffffffffu, q, o);
            }
            float mean = s * (1.0f / 64.0f);
            float inv  = rsqrtf(q * (1.0f / 64.0f) - mean * mean + LN_EPS);
            lnrel[row * 64 + lane]      = (x0 - mean) * inv;
            lnrel[row * 64 + 32 + lane] = (x1 - mean) * inv;
        }
    }

    const float4* ln4 = reinterpret_cast<const float4*>(lnrel);
    const int d4  = t & 15;
    const int jr0 = t >> 4;                   // 0..31

    while (true) {
        if (t == 0) sp = atomicAdd(&g_ctr, 1);
        __syncthreads();                       // also covers table on 1st iter
        int p = sp;
        if (p >= N_PANELS) break;

        const int b = p >> 9;
        const int i = p & 511;

        // sid for this row: each thread owns j = t
        {
            int tj = tty[b * 512 + t];
            int ti = tty[b * 512 + i];
            int id;
            if (t == i)            id = -1;           // diag: skip
            else if (i == 0)       id = 128;
            else if (t == 0)       id = 129;
            else if (tj != ti)     id = 64;
            else {
                int d = i - t;
                id = (d > 0) ? 128 - min(d, 63) : min(-d, 63);
            }
            sid[t] = (id < 0) ? -1 : (id << 4);       // float4 offset
        }
        __syncthreads();

        // stores: 16 float4/thread, explicit 4-wide batching
        float4* outp = reinterpret_cast<float4*>(out2) + (size_t)p * (512 * 16);
        #pragma unroll
        for (int g = 0; g < 4; g++) {
            int j0 = jr0 + g * 128;
            int s0 = sid[j0];
            int s1 = sid[j0 + 32];
            int s2 = sid[j0 + 64];
            int s3 = sid[j0 + 96];
            float4 v0 = ln4[max(s0, 0) + d4];
            float4 v1 = ln4[max(s1, 0) + d4];
            float4 v2 = ln4[max(s2, 0) + d4];
            float4 v3 = ln4[max(s3, 0) + d4];
            float4* o = outp + j0 * 16 + d4;
            if (s0 >= 0) __stcs(o,           v0);
            if (s1 >= 0) __stcs(o + 32 * 16, v1);
            if (s2 >= 0) __stcs(o + 64 * 16, v2);
            if (s3 >= 0) __stcs(o + 96 * 16, v3);
        }
        __syncthreads();                       // sid/sp stable until here
    }
}

// ===========================================================================
// Kernel B: compute role. 512 blocks, 8 rows each. Phase 1 warp-per-row.
// ===========================================================================
__global__ void __launch_bounds__(256) k_comp(
    const int* __restrict__ tok, const int* __restrict__ tty,
    const float* __restrict__ Wword, const float* __restrict__ Wtype,
    const float* __restrict__ Wabs,  const float* __restrict__ Wrel,
    const float* __restrict__ Wglob, const float* __restrict__ Wdiag,
    const float* __restrict__ bdiag,
    float* __restrict__ out0, float* __restrict__ out1,
    float* __restrict__ out2) {

    __shared__ float sx[8][768];
    __shared__ union {
        float sWd[64][65];
        float sred[8][8][64];
    } u;
    __shared__ float sy[8][64];

    const int t    = threadIdx.x;
    const int warp = t >> 5, lane = t & 31;
    const int cid  = blockIdx.x;
    const int row0 = cid * 8;

    if (cid < 8) {
        int g = cid * 8 + warp;
        float x0 = Wglob[g * 64 + lane];
        float x1 = Wglob[g * 64 + 32 + lane];
        float s = x0 + x1, q = x0 * x0 + x1 * x1;
        #pragma unroll
        for (int o = 16; o; o >>= 1) {
            s += __shfl_xor_sync(0xffffffffu, s, o);
            q += __shfl_xor_sync(0xffffffffu, q, o);
        }
        float mean = s * (1.0f / 64.0f);
        float inv  = rsqrtf(q * (1.0f / 64.0f) - mean * mean + LN_EPS);
        float v0 = (x0 - mean) * inv, v1 = (x1 - mean) * inv;
        #pragma unroll
        for (int bb = 0; bb < 8; bb++) {
            out0[(bb * 64 + g) * 64 + lane]      = v0;
            out0[(bb * 64 + g) * 64 + 32 + lane] = v1;
        }
    }

    // ---- phase 1: warp-per-row gather + LN (no block barriers) ----
    {
        int row = row0 + warp;
        int s   = row & 511;
        int tk  = tok[row], ty = tty[row];
        const float* pw = Wword + (size_t)tk * 768;
        const float* pt = Wtype + (size_t)ty * 768;
        const float* pa = Wabs  + (size_t)s  * 768;

        float v[24];
        float s1 = 0.f, q1 = 0.f;
        #pragma unroll
        for (int m = 0; m < 24; m++) {
            int idx = lane + 32 * m;
            float x = pw[idx] + pt[idx] + pa[idx];
            v[m] = x;
            s1 += x;
            q1 += x * x;
        }
        #pragma unroll
        for (int o = 16; o; o >>= 1) {
            s1 += __shfl_xor_sync(0xffffffffu, s1, o);
            q1 += __shfl_xor_sync(0xffffffffu, q1, o);
        }
        float mean = s1 * (1.0f / 768.0f);
        float var  = q1 * (1.0f / 768.0f) - mean * mean;
        float inv  = rsqrtf(var + LN_EPS);

        float* o = out1 + (size_t)row * 768;
        #pragma unroll
        for (int m = 0; m < 24; m++) {
            int idx = lane + 32 * m;
            sx[warp][idx] = v[m];
            o[idx] = (v[m] - mean) * inv;
        }
    }

    // ---- phase 2: diag GEMV, 8-row register blocking ----
    float acc0[8], acc1[8];
    #pragma unroll
    for (int r = 0; r < 8; r++) { acc0[r] = 0.f; acc1[r] = 0.f; }

    for (int c = 0; c < 12; c++) {
        __syncthreads();
        for (int e = t; e < 64 * 64; e += 256) {
            int k = e & 63, d = e >> 6;
            u.sWd[k][d] = Wdiag[(size_t)d * 768 + c * 64 + k];
        }
        __syncthreads();
        int kbase = warp * 8;
        #pragma unroll
        for (int kk = 0; kk < 8; kk++) {
            float w0 = u.sWd[kbase + kk][lane];
            float w1 = u.sWd[kbase + kk][lane + 32];
            int kg = c * 64 + kbase + kk;
            #pragma unroll
            for (int r = 0; r < 8; r++) {
                float xv = sx[r][kg];
                acc0[r] += xv * w0;
                acc1[r] += xv * w1;
            }
        }
    }

    __syncthreads();
    #pragma unroll
    for (int r = 0; r < 8; r++) {
        u.sred[warp][r][lane]      = acc0[r];
        u.sred[warp][r][lane + 32] = acc1[r];
    }
    __syncthreads();
    for (int o = t; o < 512; o += 256) {
        int r = o >> 6, d = o & 63;
        float s = 0.f;
        #pragma unroll
        for (int w = 0; w < 8; w++) s += u.sred[w][r][d];
        sy[r][d] = s + Wrel[d] + bdiag[d];
    }
    __syncthreads();

    {
        float y0 = sy[warp][lane];
        float y1 = sy[warp][lane + 32];
        float S = y0 + y1, Q = y0 * y0 + y1 * y1;
        #pragma unroll
        for (int o = 16; o; o >>= 1) {
            S += __shfl_xor_sync(0xffffffffu, S, o);
            Q += __shfl_xor_sync(0xffffffffu, Q, o);
        }
        float mean = S * (1.0f / 64.0f);
        float inv  = rsqrtf(Q * (1.0f / 64.0f) - mean * mean + LN_EPS);
        int row = row0 + warp;
        int s   = row & 511;
        float* od = out2 + ((size_t)row * 512 + s) * 64;
        od[lane]      = (y0 - mean) * inv;
        od[lane + 32] = (y1 - mean) * inv;
    }
}

// ---------------------------------------------------------------------------
extern "C" void kernel_launch(void* const* d_in, const int* in_sizes, int n_in,
                              void* d_out, int out_size) {
    const int*   tok   = (const int*)d_in[0];
    const int*   tty   = (const int*)d_in[1];
    const float* Wword = (const float*)d_in[2];
    const float* Wtype = (const float*)d_in[3];
    const float* Wabs  = (const float*)d_in[4];
    const float* Wrel  = (const float*)d_in[5];
    const float* Wglob = (const float*)d_in[6];
    const float* Wdiag = (const float*)d_in[7];
    const float* bdiag = (const float*)d_in[8];

    float* out  = (float*)d_out;
    float* out0 = out;                      // [8,64,64]
    float* out1 = out0 + 8 * 64 * 64;       // [8,512,768]
    float* out2 = out1 + 8 * 512 * 768;     // [8,512,512,64]

    static cudaStream_t sLo = nullptr, sHi = nullptr;
    static cudaEvent_t  efork = nullptr, e1 = nullptr, e2 = nullptr;
    static void* ctrAddr = nullptr;
    static int   grid2 = 0;
    if (!sLo) {
        int loPrio = 0, hiPrio = 0;
        cudaDeviceGetStreamPriorityRange(&loPrio, &hiPrio);
        cudaStreamCreateWithPriority(&sLo, cudaStreamNonBlocking, loPrio);
        cudaStreamCreateWithPriority(&sHi, cudaStreamNonBlocking, hiPrio);
        cudaEventCreateWithFlags(&efork, cudaEventDisableTiming);
        cudaEventCreateWithFlags(&e1, cudaEventDisableTiming);
        cudaEventCreateWithFlags(&e2, cudaEventDisableTiming);
        cudaGetSymbolAddress(&ctrAddr, g_ctr);
        int dev = 0, nsm = 148;
        cudaGetDevice(&dev);
        cudaDeviceGetAttribute(&nsm, cudaDevAttrMultiProcessorCount, dev);
        grid2 = nsm * 4;
    }

    cudaEventRecord(efork, 0);
    cudaStreamWaitEvent(sLo, efork, 0);
    cudaStreamWaitEvent(sHi, efork, 0);

    k_comp<<<512, 256, 0, sLo>>>(tok, tty, Wword, Wtype, Wabs, Wrel, Wglob,
                                 Wdiag, bdiag, out0, out1, out2);
    cudaEventRecord(e1, sLo);

    cudaMemsetAsync(ctrAddr, 0, sizeof(int), sHi);
    k_embd2<<<grid2, 512, 0, sHi>>>(tty, Wrel, out2);
    cudaEventRecord(e2, sHi);

    cudaStreamWaitEvent(0, e1, 0);
    cudaStreamWaitEvent(0, e2, 0);
}